// round 8
// baseline (speedup 1.0000x reference)
#include <cuda_runtime.h>
#include <cuda_fp16.h>
#include <math.h>
#include <stdint.h>

#define Hn 300
#define Wn 300
#define Cn 4
#define Mn 4096
#define TWO_PI_F 6.2831853071795864769f

// 3M GEMMs: P_z[m,ch] = sum_k A_z[m,k] * B_z[ch,k],  K = 320 (300 + pad), fp16
//   z=0: cos * Sr ; z=1: sin * Si ; z=2: (cos+sin) * (Sr+Si)
//   Tr = P0 - P1 ; Ti = P2 - P0 - P1
#define KT_TOT 20
#define MT_TOT 256
#define NT_TOT 160
#define CHPAD 1280
#define NCHUNK 10
#define STAGES 4

#define AP_V (KT_TOT * MT_TOT * 128)   // half2 per A variant
#define BP_V (KT_TOT * NT_TOT * 64)    // half2 per B variant
#define PS   ((size_t)Mn * CHPAD)      // halves per P variant

#define A_STAGE_BYTES 8192
#define B_STAGE_BYTES 8192
#define STAGE_BYTES (A_STAGE_BYTES + B_STAGE_BYTES)
#define SMEM_DYN (STAGES * STAGE_BYTES)   // 65536

#define S2_BLOCKS 1024    // stage2: 4 m per block, 2 warps per m

// ---------------------------------------------------------------------------
// Scratch (allocation-free rule: __device__ globals)
// ---------------------------------------------------------------------------
__device__ __align__(128) __half2 g_Ap[3 * AP_V];
__device__ __align__(128) __half2 g_Bp[3 * BP_V];
__device__ __align__(128) __half  g_P [3 * Mn * CHPAD];
__device__ float g_part[S2_BLOCKS];
__device__ unsigned int g_cnt;

// ---------------------------------------------------------------------------
// Helpers
// ---------------------------------------------------------------------------
__device__ __forceinline__ uint32_t smem_u32(const void* p) {
    uint32_t a;
    asm("{ .reg .u64 t; cvta.to.shared.u64 t, %1; cvt.u32.u64 %0, t; }" : "=r"(a) : "l"(p));
    return a;
}
#define CP_ASYNC16(dst, src) asm volatile("cp.async.cg.shared.global [%0], [%1], 16;" :: "r"(dst), "l"(src) : "memory")
#define CP_COMMIT()          asm volatile("cp.async.commit_group;" ::: "memory")
#define CP_WAIT(n)           asm volatile("cp.async.wait_group %0;" :: "n"(n) : "memory")

__device__ __forceinline__ void lds128(uint32_t* r, uint32_t a) {
    asm volatile("ld.shared.v4.b32 {%0,%1,%2,%3}, [%4];"
                 : "=r"(r[0]), "=r"(r[1]), "=r"(r[2]), "=r"(r[3]) : "r"(a));
}
__device__ __forceinline__ void lds64(uint32_t* r, uint32_t a) {
    asm volatile("ld.shared.v2.b32 {%0,%1}, [%2];" : "=r"(r[0]), "=r"(r[1]) : "r"(a));
}
__device__ __forceinline__ void mma_f16(float* c, const uint32_t* a, const uint32_t* b) {
    asm volatile(
        "mma.sync.aligned.m16n8k16.row.col.f32.f16.f16.f32 "
        "{%0,%1,%2,%3}, {%4,%5,%6,%7}, {%8,%9}, {%0,%1,%2,%3};"
        : "+f"(c[0]), "+f"(c[1]), "+f"(c[2]), "+f"(c[3])
        : "r"(a[0]), "r"(a[1]), "r"(a[2]), "r"(a[3]), "r"(b[0]), "r"(b[1]));
}

// exp(-2*pi*i * f_cycles): reduce in cycles domain, MUFU fast path.
__device__ __forceinline__ float2 phasor(float f) {
    f -= rintf(f);
    float s, c;
    __sincosf(-TWO_PI_F * f, &s, &c);
    return make_float2(c, s);
}
__device__ __forceinline__ float2 cmul(float2 a, float2 b) {
    return make_float2(a.x * b.x - a.y * b.y, a.x * b.y + a.y * b.x);
}

// ---------------------------------------------------------------------------
// Merged prep: threads [0, AP_V) build A variants, [AP_V, AP_V+BP_V) build B.
// ---------------------------------------------------------------------------
__global__ void prep_kernel(const float* __restrict__ omega,
                            const float* __restrict__ img,
                            const float* __restrict__ csm) {
    int t = blockIdx.x * blockDim.x + threadIdx.x;
    if (t < AP_V) {
        int p = t;
        int r    = p & 3;
        int lane = (p >> 2) & 31;
        int mt   = (p >> 7) & 255;
        int kt   = p >> 15;
        int m  = mt * 16 + (lane >> 2) + (r & 1) * 8;
        int k0 = kt * 16 + 2 * (lane & 3) + (r >> 1) * 8;
        float c0 = 0.f, s0 = 0.f, c1 = 0.f, s1 = 0.f;
        if (k0 < 300) {
            float om = omega[Mn + m];
            float2 e0 = phasor(om * (float)(k0 - 150));
            float2 e1 = phasor(om * (float)(k0 - 149));
            c0 = e0.x; s0 = e0.y; c1 = e1.x; s1 = e1.y;
        }
        g_Ap[p]            = __floats2half2_rn(c0, c1);
        g_Ap[AP_V + p]     = __floats2half2_rn(s0, s1);
        g_Ap[2 * AP_V + p] = __floats2half2_rn(c0 + s0, c1 + s1);
    } else if (t < AP_V + BP_V) {
        int p = t - AP_V;
        int r    = p & 1;
        int lane = (p >> 1) & 31;
        int nt   = (p >> 6) % NT_TOT;
        int kt   = p / (64 * NT_TOT);
        int ch = nt * 8 + (lane >> 2);
        int k0 = kt * 16 + 2 * (lane & 3) + r * 8;
        float sr0 = 0.f, si0 = 0.f, sr1 = 0.f, si1 = 0.f;
        if (ch < 1200 && k0 < 300) {
            int c = ch / 300;
            int h = ch - c * 300;
            int base = (c * 300 + h) * 300 + k0;
            float v0 = img[h * 300 + k0];
            float v1 = img[h * 300 + k0 + 1];
            sr0 = csm[2 * base] * v0;     si0 = csm[2 * base + 1] * v0;
            sr1 = csm[2 * base + 2] * v1; si1 = csm[2 * base + 3] * v1;
        }
        g_Bp[p]            = __floats2half2_rn(sr0, sr1);
        g_Bp[BP_V + p]     = __floats2half2_rn(si0, si1);
        g_Bp[2 * BP_V + p] = __floats2half2_rn(sr0 + si0, sr1 + si1);
    }
}

// ---------------------------------------------------------------------------
// GEMM: CTA 128x128, warp 64x32 (2x4 warps), K-chunk 32, 4-stage cp.async.
// grid: (32 mTiles, 10 nTiles, 3 variants); 2 CTAs/SM.
// ---------------------------------------------------------------------------
__global__ void __launch_bounds__(256, 2) gemm_kernel() {
    extern __shared__ __align__(128) char dsm[];
    const int tid  = threadIdx.x;
    const int wid  = tid >> 5;
    const int lane = tid & 31;
    const int warp_m = wid & 1;
    const int warp_n = wid >> 1;
    const int mTile = blockIdx.x;
    const int nTile = blockIdx.y;
    const __half2* __restrict__ Asrc = g_Ap + (size_t)blockIdx.z * AP_V;
    const __half2* __restrict__ Bsrc = g_Bp + (size_t)blockIdx.z * BP_V;
    __half* __restrict__ Pout = g_P + (size_t)blockIdx.z * PS;

    const uint32_t smem_base = smem_u32(dsm);

    float acc[4][4][4];
#pragma unroll
    for (int i = 0; i < 4; i++)
#pragma unroll
        for (int j = 0; j < 4; j++)
#pragma unroll
            for (int q = 0; q < 4; q++) acc[i][j][q] = 0.0f;

    auto load_chunk = [&](int chunk, int stage) {
        const int kt0 = chunk * 2;
        const uint32_t sA = smem_base + stage * STAGE_BYTES;
        const uint32_t sB = sA + A_STAGE_BYTES;
#pragma unroll
        for (int i = 0; i < 2; i++) {
            int s = i * 256 + tid;
            int ktl = s >> 8, mtl = (s >> 5) & 7, ls = s & 31;
            const __half2* src = Asrc +
                ((size_t)((kt0 + ktl) * MT_TOT + mTile * 8 + mtl) * 32 + ls) * 4;
            CP_ASYNC16(sA + s * 16, src);
        }
#pragma unroll
        for (int i = 0; i < 2; i++) {
            int s = i * 256 + tid;
            int ktl = s >> 8, ntl = (s >> 4) & 15, inner = s & 15;
            const __half2* src = Bsrc +
                (size_t)((kt0 + ktl) * NT_TOT + nTile * 16 + ntl) * 64 + inner * 4;
            CP_ASYNC16(sB + s * 16, src);
        }
        CP_COMMIT();
    };

    load_chunk(0, 0);
    load_chunk(1, 1);
    load_chunk(2, 2);

    for (int j = 0; j < NCHUNK; j++) {
        if (j < 8)       { CP_WAIT(2); }
        else if (j == 8) { CP_WAIT(1); }
        else             { CP_WAIT(0); }
        __syncthreads();

        const int stage = j & 3;
        const uint32_t sA = smem_base + stage * STAGE_BYTES;
        const uint32_t sB = sA + A_STAGE_BYTES;

        if (j + 3 < NCHUNK) load_chunk(j + 3, (j + 3) & 3);

#pragma unroll
        for (int ktl = 0; ktl < 2; ktl++) {
            uint32_t a[4][4], b[4][2];
#pragma unroll
            for (int i = 0; i < 4; i++)
                lds128(a[i], sA + (uint32_t)(((ktl * 8) + warp_m * 4 + i) * 32 + lane) * 16);
#pragma unroll
            for (int jn = 0; jn < 4; jn++)
                lds64(b[jn], sB + (uint32_t)(((ktl * 16) + warp_n * 4 + jn) * 32 + lane) * 8);
#pragma unroll
            for (int i = 0; i < 4; i++)
#pragma unroll
                for (int jn = 0; jn < 4; jn++)
                    mma_f16(acc[i][jn], a[i], b[jn]);
        }
    }

    // Epilogue (fp16)
    const size_t rowBase = (size_t)mTile * 128 + warp_m * 64 + (lane >> 2);
    const int colBase = nTile * 128 + warp_n * 32 + 2 * (lane & 3);
#pragma unroll
    for (int i = 0; i < 4; i++) {
        size_t r0 = rowBase + i * 16;
#pragma unroll
        for (int jn = 0; jn < 4; jn++) {
            int col = colBase + jn * 8;
            *(__half2*)&Pout[r0 * CHPAD + col] = __floats2half2_rn(acc[i][jn][0], acc[i][jn][1]);
            *(__half2*)&Pout[(r0 + 8) * CHPAD + col] = __floats2half2_rn(acc[i][jn][2], acc[i][jn][3]);
        }
    }
}

// ---------------------------------------------------------------------------
// Stage 2 (fused loss + final reduce): 4 m per block, 2 warps per m (h split).
// Tr = P0-P1, Ti = P2-P0-P1 ; k[c,m] = (1/300)*sum_h T*exp(-2pi i om0 (h-150))
// Warp pair combines partial complex k in smem; last block reduces g_part.
// ---------------------------------------------------------------------------
__global__ void __launch_bounds__(256) stage2_kernel(const float* __restrict__ omega,
                                                     const float* __restrict__ kdata,
                                                     float* __restrict__ out) {
    __shared__ float2 sacc[8][Cn];
    __shared__ float bpart[4];
    __shared__ int slast;
    const int wid = threadIdx.x >> 5;
    const int lane = threadIdx.x & 31;
    const int m = blockIdx.x * 4 + (wid >> 1);
    const int half = wid & 1;

    const float om0 = omega[m];
    const size_t rowoff = (size_t)m * CHPAD;
    const uint2* p0 = (const uint2*)(g_P + rowoff);
    const uint2* p1 = (const uint2*)(g_P + PS + rowoff);
    const uint2* p2 = (const uint2*)(g_P + 2 * PS + rowoff);

    const int start = half * 38;          // half0: [0,38) ; half1: [38,75)
    const int end   = half ? 75 : 38;

    float2 e    = phasor(om0 * (float)(4 * (start + lane) - 150));
    float2 e1   = phasor(om0);
    float2 e2   = cmul(e1, e1);
    float2 e3   = cmul(e2, e1);
    float2 step = phasor(om0 * 128.0f);

    float2 acc[Cn] = {{0,0},{0,0},{0,0},{0,0}};

    for (int idx = start + lane; idx < end; idx += 32) {
        uint2 a0[Cn], a1[Cn], a2[Cn];
#pragma unroll
        for (int c = 0; c < Cn; c++) {
            a0[c] = p0[c * 75 + idx];
            a1[c] = p1[c * 75 + idx];
            a2[c] = p2[c * 75 + idx];
        }
#pragma unroll
        for (int c = 0; c < Cn; c++) {
            float2 q0a = __half22float2(*(__half2*)&a0[c].x);
            float2 q0b = __half22float2(*(__half2*)&a0[c].y);
            float2 q1a = __half22float2(*(__half2*)&a1[c].x);
            float2 q1b = __half22float2(*(__half2*)&a1[c].y);
            float2 q2a = __half22float2(*(__half2*)&a2[c].x);
            float2 q2b = __half22float2(*(__half2*)&a2[c].y);

            float tr0 = q0a.x - q1a.x, ti0 = q2a.x - q0a.x - q1a.x;
            float tr1 = q0a.y - q1a.y, ti1 = q2a.y - q0a.y - q1a.y;
            float tr2 = q0b.x - q1b.x, ti2 = q2b.x - q0b.x - q1b.x;
            float tr3 = q0b.y - q1b.y, ti3 = q2b.y - q0b.y - q1b.y;

            float qr = tr0 + tr1 * e1.x - ti1 * e1.y + tr2 * e2.x - ti2 * e2.y
                           + tr3 * e3.x - ti3 * e3.y;
            float qi = ti0 + tr1 * e1.y + ti1 * e1.x + tr2 * e2.y + ti2 * e2.x
                           + tr3 * e3.y + ti3 * e3.x;

            acc[c].x += e.x * qr - e.y * qi;
            acc[c].y += e.x * qi + e.y * qr;
        }
        e = cmul(e, step);
    }

#pragma unroll
    for (int off = 16; off; off >>= 1)
#pragma unroll
        for (int c = 0; c < Cn; c++) {
            acc[c].x += __shfl_down_sync(0xffffffffu, acc[c].x, off);
            acc[c].y += __shfl_down_sync(0xffffffffu, acc[c].y, off);
        }
    if (lane == 0)
#pragma unroll
        for (int c = 0; c < Cn; c++) sacc[wid][c] = acc[c];
    __syncthreads();

    if (half == 0 && lane == 0) {
        const float inv = 1.0f / 300.0f;
        float o0 = om0 * TWO_PI_F;
        float o1 = omega[Mn + m] * TWO_PI_F;
        float wgt = sqrtf(o0 * o0 + o1 * o1) + 1.0f;
        float w2 = wgt * wgt;
        float s = 0.0f;
#pragma unroll
        for (int c = 0; c < Cn; c++) {
            float kr = (sacc[wid][c].x + sacc[wid + 1][c].x) * inv;
            float ki = (sacc[wid][c].y + sacc[wid + 1][c].y) * inv;
            float dr = kr - kdata[2 * (c * Mn + m)];
            float di = ki - kdata[2 * (c * Mn + m) + 1];
            s += w2 * (dr * dr + di * di);
        }
        bpart[wid >> 1] = s;
    }
    __syncthreads();
    if (threadIdx.x == 0) {
        g_part[blockIdx.x] = bpart[0] + bpart[1] + bpart[2] + bpart[3];
        __threadfence();
        unsigned int t = atomicAdd(&g_cnt, 1u);
        slast = (t == (unsigned int)(gridDim.x - 1)) ? 1 : 0;
    }
    __syncthreads();

    if (slast) {
        __shared__ float red[256];
        float s = 0.0f;
        for (int i = threadIdx.x; i < S2_BLOCKS; i += 256) s += g_part[i];
        red[threadIdx.x] = s;
        __syncthreads();
        for (int off = 128; off; off >>= 1) {
            if (threadIdx.x < off) red[threadIdx.x] += red[threadIdx.x + off];
            __syncthreads();
        }
        if (threadIdx.x == 0) {
            out[0] = red[0] / (float)(2 * Cn * Mn);
            g_cnt = 0;   // reset for next replay (deterministic)
        }
    }
}

// ---------------------------------------------------------------------------
extern "C" void kernel_launch(void* const* d_in, const int* in_sizes, int n_in,
                              void* d_out, int out_size) {
    const float* img   = (const float*)d_in[0];   // (300,300,1)
    const float* kdata = (const float*)d_in[1];   // (1,4,4096,2)
    const float* omega = (const float*)d_in[2];   // (1,2,4096)
    const float* csm   = (const float*)d_in[4];   // (4,300,300,2)
    float* out = (float*)d_out;

    prep_kernel<<<(AP_V + BP_V + 255) / 256, 256>>>(omega, img, csm);

    cudaFuncSetAttribute(gemm_kernel, cudaFuncAttributeMaxDynamicSharedMemorySize, SMEM_DYN);
    gemm_kernel<<<dim3(Mn / 128, CHPAD / 128, 3), 256, SMEM_DYN>>>();

    stage2_kernel<<<S2_BLOCKS, 256>>>(omega, kdata, out);
}

// round 9
// speedup vs baseline: 1.3174x; 1.3174x over previous
#include <cuda_runtime.h>
#include <cuda_fp16.h>
#include <math.h>
#include <stdint.h>

#define Hn 300
#define Wn 300
#define Cn 4
#define Mn 4096
#define TWO_PI_F 6.2831853071795864769f

// Folded-symmetry GEMMs (x = |w-150|):
//   A[m,k] = k<=150 ? cos(2pi om1 k) : k<=300 ? sin(2pi om1 (k-150)) : 0
//   B0[ch,k] = k<=150 ? Pr[x=k] : Mi[x=k-150]     -> P0 row = Tr
//   B1[ch,k] = k<=150 ? Pi[x=k] : -Mr[x=k-150]    -> P1 row = Ti
//   P = S(x)+S(-x), M = S(x)-S(-x)  (S(w') = sim at w = 150+w'; S(150)=0, x=0 single)
#define KT_TOT 20          // K tiles of 16 -> K=320 (301 used)
#define MT_TOT 256
#define NT_TOT 160
#define CHPAD 1280
#define NCHUNK 10
#define STAGES 4

#define AP_V (KT_TOT * MT_TOT * 128)   // half2, single A (shared by both GEMMs)
#define BP_V (KT_TOT * NT_TOT * 64)    // half2 per B variant
#define PS   ((size_t)Mn * CHPAD)      // halves per P variant

#define A_STAGE_BYTES 8192
#define B_STAGE_BYTES 8192
#define STAGE_BYTES (A_STAGE_BYTES + B_STAGE_BYTES)
#define SMEM_DYN (STAGES * STAGE_BYTES)   // 65536

#define S2_BLOCKS 1024    // stage2: 4 m per block, 2 warps per m (coil split)

// ---------------------------------------------------------------------------
// Scratch (allocation-free rule: __device__ globals)
// ---------------------------------------------------------------------------
__device__ __align__(128) __half2 g_Ap[AP_V];
__device__ __align__(128) __half2 g_Bp[2 * BP_V];
__device__ __align__(128) __half  g_P [2 * Mn * CHPAD];   // Tr, Ti (21 MB)
__device__ float g_part[S2_BLOCKS];
__device__ unsigned int g_cnt;

// ---------------------------------------------------------------------------
// Helpers
// ---------------------------------------------------------------------------
__device__ __forceinline__ uint32_t smem_u32(const void* p) {
    uint32_t a;
    asm("{ .reg .u64 t; cvta.to.shared.u64 t, %1; cvt.u32.u64 %0, t; }" : "=r"(a) : "l"(p));
    return a;
}
#define CP_ASYNC16(dst, src) asm volatile("cp.async.cg.shared.global [%0], [%1], 16;" :: "r"(dst), "l"(src) : "memory")
#define CP_COMMIT()          asm volatile("cp.async.commit_group;" ::: "memory")
#define CP_WAIT(n)           asm volatile("cp.async.wait_group %0;" :: "n"(n) : "memory")

__device__ __forceinline__ void lds128(uint32_t* r, uint32_t a) {
    asm volatile("ld.shared.v4.b32 {%0,%1,%2,%3}, [%4];"
                 : "=r"(r[0]), "=r"(r[1]), "=r"(r[2]), "=r"(r[3]) : "r"(a));
}
__device__ __forceinline__ void lds64(uint32_t* r, uint32_t a) {
    asm volatile("ld.shared.v2.b32 {%0,%1}, [%2];" : "=r"(r[0]), "=r"(r[1]) : "r"(a));
}
__device__ __forceinline__ void mma_f16(float* c, const uint32_t* a, const uint32_t* b) {
    asm volatile(
        "mma.sync.aligned.m16n8k16.row.col.f32.f16.f16.f32 "
        "{%0,%1,%2,%3}, {%4,%5,%6,%7}, {%8,%9}, {%0,%1,%2,%3};"
        : "+f"(c[0]), "+f"(c[1]), "+f"(c[2]), "+f"(c[3])
        : "r"(a[0]), "r"(a[1]), "r"(a[2]), "r"(a[3]), "r"(b[0]), "r"(b[1]));
}

// (cos, sin) of +2*pi*f, cycles-domain reduction + MUFU fast path
__device__ __forceinline__ float2 phasor_pos(float f) {
    f -= rintf(f);
    float s, c;
    __sincosf(TWO_PI_F * f, &s, &c);
    return make_float2(c, s);
}
// (cos, sin) of -2*pi*f
__device__ __forceinline__ float2 phasor(float f) {
    float2 e = phasor_pos(f);
    return make_float2(e.x, -e.y);
}
__device__ __forceinline__ float2 cmul(float2 a, float2 b) {
    return make_float2(a.x * b.x - a.y * b.y, a.x * b.y + a.y * b.x);
}

// A element value
__device__ __forceinline__ float a_val(int k, float om) {
    if (k <= 150) return phasor_pos(om * (float)k).x;          // cos
    if (k <= 300) return phasor_pos(om * (float)(k - 150)).y;  // sin
    return 0.0f;
}

// ---------------------------------------------------------------------------
// Merged prep: threads [0, AP_V) build A, [AP_V, AP_V+BP_V) build B variants.
// ---------------------------------------------------------------------------
__global__ void prep_kernel(const float* __restrict__ omega,
                            const float* __restrict__ img,
                            const float* __restrict__ csm) {
    int t = blockIdx.x * blockDim.x + threadIdx.x;
    if (t < AP_V) {
        int p = t;
        int r    = p & 3;
        int lane = (p >> 2) & 31;
        int mt   = (p >> 7) & 255;
        int kt   = p >> 15;
        int m  = mt * 16 + (lane >> 2) + (r & 1) * 8;
        int k0 = kt * 16 + 2 * (lane & 3) + (r >> 1) * 8;
        float om = omega[Mn + m];
        g_Ap[p] = __floats2half2_rn(a_val(k0, om), a_val(k0 + 1, om));
    } else if (t < AP_V + BP_V) {
        int p = t - AP_V;
        int r    = p & 1;
        int lane = (p >> 1) & 31;
        int nt   = (p >> 6) % NT_TOT;
        int kt   = p / (64 * NT_TOT);
        int ch = nt * 8 + (lane >> 2);
        int k0 = kt * 16 + 2 * (lane & 3) + r * 8;
        float b0[2] = {0.f, 0.f}, b1[2] = {0.f, 0.f};
        if (ch < 1200) {
            int c = ch / 300;
            int h = ch - c * 300;
            const float* csmrow = csm + 2 * (size_t)(c * 300 + h) * 300;
            const float* imgrow = img + h * 300;
#pragma unroll
            for (int q = 0; q < 2; q++) {
                int k = k0 + q;
                if (k > 300) continue;
                if (k == 0) {
                    float v = imgrow[150];
                    b0[q] = csmrow[300] * v;       // Sr[150]
                    b1[q] = csmrow[301] * v;       // Si[150]
                } else {
                    int x  = (k <= 150) ? k : (k - 150);
                    int wm = 150 - x;
                    float vm = imgrow[wm];
                    float srm = csmrow[2 * wm] * vm;
                    float sim = csmrow[2 * wm + 1] * vm;
                    float srp = 0.f, sip = 0.f;
                    if (x <= 149) {
                        int wp = 150 + x;
                        float vp = imgrow[wp];
                        srp = csmrow[2 * wp] * vp;
                        sip = csmrow[2 * wp + 1] * vp;
                    }
                    if (k <= 150) { b0[q] = srp + srm;  b1[q] = sip + sim; }   // Pr, Pi
                    else          { b0[q] = sip - sim;  b1[q] = srm - srp; }   // Mi, -Mr
                }
            }
        }
        g_Bp[p]        = __floats2half2_rn(b0[0], b0[1]);
        g_Bp[BP_V + p] = __floats2half2_rn(b1[0], b1[1]);
    }
}

// ---------------------------------------------------------------------------
// GEMM: CTA 128x128, warp 64x32 (2x4 warps), K-chunk 32, 4-stage cp.async.
// grid: (32 mTiles, 10 nTiles, 2 variants); 2 CTAs/SM. A shared across z.
// ---------------------------------------------------------------------------
__global__ void __launch_bounds__(256, 2) gemm_kernel() {
    extern __shared__ __align__(128) char dsm[];
    const int tid  = threadIdx.x;
    const int wid  = tid >> 5;
    const int lane = tid & 31;
    const int warp_m = wid & 1;
    const int warp_n = wid >> 1;
    const int mTile = blockIdx.x;
    const int nTile = blockIdx.y;
    const __half2* __restrict__ Bsrc = g_Bp + (size_t)blockIdx.z * BP_V;
    __half* __restrict__ Pout = g_P + (size_t)blockIdx.z * PS;

    const uint32_t smem_base = smem_u32(dsm);

    float acc[4][4][4];
#pragma unroll
    for (int i = 0; i < 4; i++)
#pragma unroll
        for (int j = 0; j < 4; j++)
#pragma unroll
            for (int q = 0; q < 4; q++) acc[i][j][q] = 0.0f;

    auto load_chunk = [&](int chunk, int stage) {
        const int kt0 = chunk * 2;
        const uint32_t sA = smem_base + stage * STAGE_BYTES;
        const uint32_t sB = sA + A_STAGE_BYTES;
#pragma unroll
        for (int i = 0; i < 2; i++) {
            int s = i * 256 + tid;
            int ktl = s >> 8, mtl = (s >> 5) & 7, ls = s & 31;
            const __half2* src = g_Ap +
                ((size_t)((kt0 + ktl) * MT_TOT + mTile * 8 + mtl) * 32 + ls) * 4;
            CP_ASYNC16(sA + s * 16, src);
        }
#pragma unroll
        for (int i = 0; i < 2; i++) {
            int s = i * 256 + tid;
            int ktl = s >> 8, ntl = (s >> 4) & 15, inner = s & 15;
            const __half2* src = Bsrc +
                (size_t)((kt0 + ktl) * NT_TOT + nTile * 16 + ntl) * 64 + inner * 4;
            CP_ASYNC16(sB + s * 16, src);
        }
        CP_COMMIT();
    };

    load_chunk(0, 0);
    load_chunk(1, 1);
    load_chunk(2, 2);

    for (int j = 0; j < NCHUNK; j++) {
        if (j < 8)       { CP_WAIT(2); }
        else if (j == 8) { CP_WAIT(1); }
        else             { CP_WAIT(0); }
        __syncthreads();

        const int stage = j & 3;
        const uint32_t sA = smem_base + stage * STAGE_BYTES;
        const uint32_t sB = sA + A_STAGE_BYTES;

        if (j + 3 < NCHUNK) load_chunk(j + 3, (j + 3) & 3);

#pragma unroll
        for (int ktl = 0; ktl < 2; ktl++) {
            uint32_t a[4][4], b[4][2];
#pragma unroll
            for (int i = 0; i < 4; i++)
                lds128(a[i], sA + (uint32_t)(((ktl * 8) + warp_m * 4 + i) * 32 + lane) * 16);
#pragma unroll
            for (int jn = 0; jn < 4; jn++)
                lds64(b[jn], sB + (uint32_t)(((ktl * 16) + warp_n * 4 + jn) * 32 + lane) * 8);
#pragma unroll
            for (int i = 0; i < 4; i++)
#pragma unroll
                for (int jn = 0; jn < 4; jn++)
                    mma_f16(acc[i][jn], a[i], b[jn]);
        }
    }

    // Epilogue (fp16)
    const size_t rowBase = (size_t)mTile * 128 + warp_m * 64 + (lane >> 2);
    const int colBase = nTile * 128 + warp_n * 32 + 2 * (lane & 3);
#pragma unroll
    for (int i = 0; i < 4; i++) {
        size_t r0 = rowBase + i * 16;
#pragma unroll
        for (int jn = 0; jn < 4; jn++) {
            int col = colBase + jn * 8;
            *(__half2*)&Pout[r0 * CHPAD + col] = __floats2half2_rn(acc[i][jn][0], acc[i][jn][1]);
            *(__half2*)&Pout[(r0 + 8) * CHPAD + col] = __floats2half2_rn(acc[i][jn][2], acc[i][jn][3]);
        }
    }
}

// ---------------------------------------------------------------------------
// Stage 2 (fused loss + final reduce): 4 m per block, 2 warps per m,
// each warp owns 2 coils (full h range -> complete k, no cross-warp combine).
// k[c,m] = (1/300)*sum_h (Tr + i Ti)[m, c*300+h] * exp(-2pi i om0 (h-150))
// ---------------------------------------------------------------------------
__global__ void __launch_bounds__(256) stage2_kernel(const float* __restrict__ omega,
                                                     const float* __restrict__ kdata,
                                                     float* __restrict__ out) {
    __shared__ float bpart[8];
    __shared__ int slast;
    const int wid = threadIdx.x >> 5;
    const int lane = threadIdx.x & 31;
    const int m = blockIdx.x * 4 + (wid >> 1);
    const int cp = wid & 1;               // coil pair: coils {2cp, 2cp+1}

    const float om0 = omega[m];
    const size_t rowoff = (size_t)m * CHPAD;
    const uint2* pr = (const uint2*)(g_P + rowoff) + cp * 150;        // coil 2cp
    const uint2* pi = (const uint2*)(g_P + PS + rowoff) + cp * 150;

    float2 e    = phasor(om0 * (float)(4 * lane - 150));
    float2 e1   = phasor(om0);
    float2 e2   = cmul(e1, e1);
    float2 e3   = cmul(e2, e1);
    float2 step = phasor(om0 * 128.0f);

    float2 acc[2] = {{0, 0}, {0, 0}};

    for (int idx = lane; idx < 75; idx += 32) {
        uint2 ar[2], ai[2];
#pragma unroll
        for (int q = 0; q < 2; q++) {
            ar[q] = pr[q * 75 + idx];
            ai[q] = pi[q * 75 + idx];
        }
#pragma unroll
        for (int q = 0; q < 2; q++) {
            float2 ra = __half22float2(*(__half2*)&ar[q].x);
            float2 rb = __half22float2(*(__half2*)&ar[q].y);
            float2 ia = __half22float2(*(__half2*)&ai[q].x);
            float2 ib = __half22float2(*(__half2*)&ai[q].y);

            float qr = ra.x + ra.y * e1.x - ia.y * e1.y + rb.x * e2.x - ib.x * e2.y
                            + rb.y * e3.x - ib.y * e3.y;
            float qi = ia.x + ra.y * e1.y + ia.y * e1.x + rb.x * e2.y + ib.x * e2.x
                            + rb.y * e3.y + ib.y * e3.x;

            acc[q].x += e.x * qr - e.y * qi;
            acc[q].y += e.x * qi + e.y * qr;
        }
        e = cmul(e, step);
    }

#pragma unroll
    for (int off = 16; off; off >>= 1)
#pragma unroll
        for (int q = 0; q < 2; q++) {
            acc[q].x += __shfl_down_sync(0xffffffffu, acc[q].x, off);
            acc[q].y += __shfl_down_sync(0xffffffffu, acc[q].y, off);
        }

    if (lane == 0) {
        const float inv = 1.0f / 300.0f;
        float o0 = om0 * TWO_PI_F;
        float o1 = omega[Mn + m] * TWO_PI_F;
        float wgt = sqrtf(o0 * o0 + o1 * o1) + 1.0f;
        float w2 = wgt * wgt;
        float s = 0.0f;
#pragma unroll
        for (int q = 0; q < 2; q++) {
            int c = cp * 2 + q;
            float dr = acc[q].x * inv - kdata[2 * (c * Mn + m)];
            float di = acc[q].y * inv - kdata[2 * (c * Mn + m) + 1];
            s += w2 * (dr * dr + di * di);
        }
        bpart[wid] = s;
    }
    __syncthreads();
    if (threadIdx.x == 0) {
        float s = 0.0f;
#pragma unroll
        for (int w = 0; w < 8; w++) s += bpart[w];
        g_part[blockIdx.x] = s;
        __threadfence();
        unsigned int t = atomicAdd(&g_cnt, 1u);
        slast = (t == (unsigned int)(gridDim.x - 1)) ? 1 : 0;
    }
    __syncthreads();

    if (slast) {
        __shared__ float red[256];
        float s = 0.0f;
        for (int i = threadIdx.x; i < S2_BLOCKS; i += 256) s += g_part[i];
        red[threadIdx.x] = s;
        __syncthreads();
        for (int off = 128; off; off >>= 1) {
            if (threadIdx.x < off) red[threadIdx.x] += red[threadIdx.x + off];
            __syncthreads();
        }
        if (threadIdx.x == 0) {
            out[0] = red[0] / (float)(2 * Cn * Mn);
            g_cnt = 0;   // reset for next replay (deterministic)
        }
    }
}

// ---------------------------------------------------------------------------
extern "C" void kernel_launch(void* const* d_in, const int* in_sizes, int n_in,
                              void* d_out, int out_size) {
    const float* img   = (const float*)d_in[0];   // (300,300,1)
    const float* kdata = (const float*)d_in[1];   // (1,4,4096,2)
    const float* omega = (const float*)d_in[2];   // (1,2,4096)
    const float* csm   = (const float*)d_in[4];   // (4,300,300,2)
    float* out = (float*)d_out;

    prep_kernel<<<(AP_V + BP_V + 255) / 256, 256>>>(omega, img, csm);

    cudaFuncSetAttribute(gemm_kernel, cudaFuncAttributeMaxDynamicSharedMemorySize, SMEM_DYN);
    gemm_kernel<<<dim3(Mn / 128, CHPAD / 128, 2), 256, SMEM_DYN>>>();

    stage2_kernel<<<S2_BLOCKS, 256>>>(omega, kdata, out);
}